// round 6
// baseline (speedup 1.0000x reference)
#include <cuda_runtime.h>

// Problem constants
#define Bq 4
#define Hq 256
#define Wq 256
#define Zq 64
#define ITER 8
#define EPS 1e-6

constexpr int N    = Bq * Hq * Wq * Zq;   // 16,777,216
#define NT 256
constexpr int NBLK = N / 4 / NT;          // 16384 blocks, 4 elems/thread

// Scratch (device globals: allocation is forbidden)
__device__ float g_ra[N];        // ping-pong r buffers (r_it for it>=1)
__device__ float g_rb[N];
__device__ float g_p[ITER][N];   // all search directions kept for lazy-x

__device__ double   g_rho[ITER + 1][Bq];
__device__ double   g_eta[ITER][Bq];
__device__ double   g_loss;
__device__ unsigned g_max;

// r0 aliases g_p[0]; for it >= 1 r_it lives in rbuf(it):
__device__ __forceinline__ float* rbuf(int it) {
    return (it & 1) ? g_rb : g_ra;
}

// ---------------------------------------------------------------------------
// helpers
// ---------------------------------------------------------------------------

__device__ __forceinline__ float4 ld4(const float* __restrict__ p) {
    return *reinterpret_cast<const float4*>(p);
}
__device__ __forceinline__ float4 ld4cs(const float* __restrict__ p) {
    return __ldcs(reinterpret_cast<const float4*>(p));
}
__device__ __forceinline__ void st4(float* __restrict__ p, float4 v) {
    *reinterpret_cast<float4*>(p) = v;
}

// 7-point Laplacian on 4 consecutive z-elements at linear index i.
// z-neighbors from adjacent lanes via shuffle (16 lanes tile one z-line).
__device__ __forceinline__ float4 stencil4(const float* __restrict__ in,
                                           int i, int z0, int wi, int h,
                                           float4* cen) {
    float4 c = ld4(in + i);
    *cen = c;
    float zl = __shfl_up_sync(0xffffffffu, c.w, 1);
    float zr = __shfl_down_sync(0xffffffffu, c.x, 1);
    if (z0 == 0)  zl = 0.f;
    if (z0 == 60) zr = 0.f;
    float4 z4 = make_float4(0.f, 0.f, 0.f, 0.f);
    float4 xm = (wi > 0)      ? ld4(in + i - Zq)      : z4;
    float4 xp = (wi < Wq - 1) ? ld4(in + i + Zq)      : z4;
    float4 ym = (h  > 0)      ? ld4(in + i - Wq * Zq) : z4;
    float4 yp = (h  < Hq - 1) ? ld4(in + i + Wq * Zq) : z4;
    float4 o;
    o.x = 6.f * c.x - xm.x - xp.x - ym.x - yp.x - zl  - c.y;
    o.y = 6.f * c.y - xm.y - xp.y - ym.y - yp.y - c.x - c.z;
    o.z = 6.f * c.z - xm.z - xp.z - ym.z - yp.z - c.y - c.w;
    o.w = 6.f * c.w - xm.w - xp.w - ym.w - yp.w - c.z - zr;
    return o;
}

__device__ __forceinline__ void block_reduce_add(float val, double* target) {
    #pragma unroll
    for (int o = 16; o; o >>= 1)
        val += __shfl_xor_sync(0xffffffffu, val, o);
    __shared__ double sh[NT / 32];
    int lane = threadIdx.x & 31, wid = threadIdx.x >> 5;
    if (lane == 0) sh[wid] = (double)val;
    __syncthreads();
    if (threadIdx.x == 0) {
        double s = 0.0;
        #pragma unroll
        for (int k = 0; k < NT / 32; ++k) s += sh[k];
        atomicAdd(target, s);
    }
}

__device__ __forceinline__ void block_reduce_max(float val, unsigned* target) {
    #pragma unroll
    for (int o = 16; o; o >>= 1)
        val = fmaxf(val, __shfl_xor_sync(0xffffffffu, val, o));
    __shared__ float shm[NT / 32];
    int lane = threadIdx.x & 31, wid = threadIdx.x >> 5;
    if (lane == 0) shm[wid] = val;
    __syncthreads();
    if (threadIdx.x == 0) {
        float m = 0.f;
        #pragma unroll
        for (int k = 0; k < NT / 32; ++k) m = fmaxf(m, shm[k]);
        atomicMax(target, __float_as_uint(m));
    }
}

// REV: sweep blocks in descending order (zigzag cross-kernel L2 reuse).
template <bool REV>
__device__ __forceinline__ void decode(int& i, int& z0, int& wi,
                                       int& h, int& b) {
    int blk = REV ? (NBLK - 1 - (int)blockIdx.x) : (int)blockIdx.x;
    int tid = blk * NT + threadIdx.x;
    i  = tid * 4;
    z0 = i & 63;
    wi = (i >> 6) & 255;
    h  = (i >> 14) & 255;
    b  = i >> 22;
}

// ---------------------------------------------------------------------------
// kernels
// ---------------------------------------------------------------------------

__global__ void k_zero() {
    int t = threadIdx.x;
    if (t < (ITER + 1) * Bq) ((double*)g_rho)[t] = 0.0;
    if (t < ITER * Bq)       ((double*)g_eta)[t] = 0.0;
    if (t == 0) { g_loss = 0.0; g_max = 0u; }
}

// p0 = r0 = b - A*x0 ; rho0 += r0.r0   (ascending; r0 aliases g_p[0])
__global__ void __launch_bounds__(NT, 8)
k_init(const float* __restrict__ xin, const float* __restrict__ bin) {
    int i, z0, wi, h, b;
    decode<false>(i, z0, wi, h, b);
    float4 c;
    float4 ax = stencil4(xin, i, z0, wi, h, &c);
    float4 bb = ld4cs(bin + i);
    float4 r  = make_float4(bb.x - ax.x, bb.y - ax.y, bb.z - ax.z, bb.w - ax.w);
    st4(g_p[0] + i, r);
    float d = r.x * r.x + r.y * r.y + r.z * r.z + r.w * r.w;
    block_reduce_add(d, &g_rho[0][b]);
}

// eta kernel (descending). Pure read, no array stores.
// FIRST: eta0 = p0 . A p0
// else : beta = rho[it]/rho[it-1]; pn = r_it + beta*p_{it-1} (registers);
//        A pn = A r + beta*A p_old;  eta[it] += pn . A pn
template <bool FIRST>
__global__ void __launch_bounds__(NT, 8)
k_eta(int it) {
    int i, z0, wi, h, b;
    decode<true>(i, z0, wi, h, b);

    if (FIRST) {
        float4 c;
        float4 w = stencil4(g_p[0], i, z0, wi, h, &c);
        float d = c.x * w.x + c.y * w.y + c.z * w.z + c.w * w.w;
        block_reduce_add(d, &g_eta[0][b]);
    } else {
        float bt = (float)(g_rho[it][b] / (g_rho[it - 1][b] + EPS));
        const float* rin = rbuf(it);
        float4 cr, cp;
        float4 wr = stencil4(rin, i, z0, wi, h, &cr);
        float4 wp = stencil4(g_p[it - 1], i, z0, wi, h, &cp);
        float4 pn = make_float4(cr.x + bt * cp.x, cr.y + bt * cp.y,
                                cr.z + bt * cp.z, cr.w + bt * cp.w);
        float4 w  = make_float4(wr.x + bt * wp.x, wr.y + bt * wp.y,
                                wr.z + bt * wp.z, wr.w + bt * wp.w);
        float d = pn.x * w.x + pn.y * w.y + pn.z * w.z + pn.w * w.w;
        block_reduce_add(d, &g_eta[it][b]);
    }
}

// update kernel (ascending). alpha = rho[it]/(eta[it]+eps)
// FIRST: r1 = p0 - alpha*A p0 -> rbuf(1). p0 already stored.
// else : pn = r_it + beta*p_{it-1}; A pn = A r + beta*A p_old (same FMAs
//        as eta, bit-identical); write g_p[it] = pn;
//        r_{it+1} = r_it - alpha*A pn -> rbuf(it+1) (different buffer:
//        parity of it+1 != parity of it, so no read/write hazard).
//        rho[it+1] += r_new.r_new
template <bool FIRST, bool LAST>
__global__ void __launch_bounds__(NT, 8)
k_update(int it) {
    int i, z0, wi, h, b;
    decode<false>(i, z0, wi, h, b);

    float a = (float)(g_rho[it][b] / (g_eta[it][b] + EPS));

    float4 r;
    if (FIRST) {
        float4 c;
        float4 w = stencil4(g_p[0], i, z0, wi, h, &c);
        r = make_float4(c.x - a * w.x, c.y - a * w.y,
                        c.z - a * w.z, c.w - a * w.w);
        st4(rbuf(1) + i, r);
    } else {
        float bt = (float)(g_rho[it][b] / (g_rho[it - 1][b] + EPS));
        const float* rin = rbuf(it);
        float4 cr, cp;
        float4 wr = stencil4(rin, i, z0, wi, h, &cr);
        float4 wp = stencil4(g_p[it - 1], i, z0, wi, h, &cp);
        float4 pn = make_float4(cr.x + bt * cp.x, cr.y + bt * cp.y,
                                cr.z + bt * cp.z, cr.w + bt * cp.w);
        float4 w  = make_float4(wr.x + bt * wp.x, wr.y + bt * wp.y,
                                wr.z + bt * wp.z, wr.w + bt * wp.w);
        st4(g_p[it] + i, pn);
        r = make_float4(cr.x - a * w.x, cr.y - a * w.y,
                        cr.z - a * w.z, cr.w - a * w.w);
        if (!LAST) st4(rbuf(it + 1) + i, r);
    }
    float d = r.x * r.x + r.y * r.y + r.z * r.z + r.w * r.w;
    block_reduce_add(d, &g_rho[it + 1][b]);
}

// final (descending): x = x0 + sum_k alpha_k p_k ; out, loss, max_error
__global__ void __launch_bounds__(NT, 8)
k_final(const float* __restrict__ xin, const float* __restrict__ ref,
        float* __restrict__ out) {
    int i, z0, wi, h, b;
    decode<true>(i, z0, wi, h, b);

    float4 x = ld4cs(xin + i);
    #pragma unroll
    for (int k = 0; k < ITER; ++k) {
        float a = (float)(g_rho[k][b] / (g_eta[k][b] + EPS));
        float4 pk = ld4cs(g_p[k] + i);
        x.x += a * pk.x; x.y += a * pk.y;
        x.z += a * pk.z; x.w += a * pk.w;
    }
    __stcs(out + 1 + i + 0, x.x);
    __stcs(out + 1 + i + 1, x.y);
    __stcs(out + 1 + i + 2, x.z);
    __stcs(out + 1 + i + 3, x.w);

    float4 rf = ld4cs(ref + i);
    float dx = x.x - rf.x, dy = x.y - rf.y;
    float dz = x.z - rf.z, dw = x.w - rf.w;
    float ss = dx * dx + dy * dy + dz * dz + dw * dw;
    float mx = fmaxf(fmaxf(fabsf(dx), fabsf(dy)),
                     fmaxf(fabsf(dz), fabsf(dw)));
    block_reduce_add(ss, &g_loss);
    block_reduce_max(mx, &g_max);
}

__global__ void k_writeout(float* __restrict__ out) {
    out[0] = (float)(g_loss / (double)N);
    out[N + 1] = __uint_as_float(g_max);
    double s = 0.0;
    #pragma unroll
    for (int b = 0; b < Bq; ++b) s += g_rho[ITER][b];
    out[N + 2] = (float)(s / (double)Bq);
}

// ---------------------------------------------------------------------------

extern "C" void kernel_launch(void* const* d_in, const int* in_sizes, int n_in,
                              void* d_out, int out_size) {
    const float* x   = (const float*)d_in[0];
    const float* b   = (const float*)d_in[1];
    const float* ref = (const float*)d_in[2];
    float* out = (float*)d_out;

    k_zero<<<1, 64>>>();
    k_init<<<NBLK, NT>>>(x, b);

    k_eta<true><<<NBLK, NT>>>(0);
    k_update<true, false><<<NBLK, NT>>>(0);

    for (int it = 1; it < ITER - 1; ++it) {
        k_eta<false><<<NBLK, NT>>>(it);
        k_update<false, false><<<NBLK, NT>>>(it);
    }

    k_eta<false><<<NBLK, NT>>>(ITER - 1);
    k_update<false, true><<<NBLK, NT>>>(ITER - 1);

    k_final<<<NBLK, NT>>>(x, ref, out);
    k_writeout<<<1, 1>>>(out);
}

// round 7
// speedup vs baseline: 2.6890x; 2.6890x over previous
#include <cuda_runtime.h>

// Problem constants
#define Bq 4
#define Hq 256
#define Wq 256
#define Zq 64
#define ITER 8
#define EPS 1e-6

constexpr int N    = Bq * Hq * Wq * Zq;   // 16,777,216
#define NT 256
constexpr int NBLK = N / 4 / NT;          // 16384 blocks, 4 elems/thread

// Scratch (device globals: allocation is forbidden)
__device__ float g_ra[N];        // ping-pong r buffers (r_it for it>=1)
__device__ float g_rb[N];
__device__ float g_p[ITER][N];   // all search directions kept for lazy-x

__device__ double   g_rho[ITER + 1][Bq];
__device__ double   g_eta[ITER][Bq];
__device__ double   g_loss;
__device__ unsigned g_max;

// r0 aliases g_p[0]; for it >= 1 r_it lives in rbuf(it):
__device__ __forceinline__ float* rbuf(int it) {
    return (it & 1) ? g_rb : g_ra;
}

// ---------------------------------------------------------------------------
// helpers
// ---------------------------------------------------------------------------

__device__ __forceinline__ float4 ld4(const float* __restrict__ p) {
    return *reinterpret_cast<const float4*>(p);
}
__device__ __forceinline__ float4 ld4cs(const float* __restrict__ p) {
    return __ldcs(reinterpret_cast<const float4*>(p));
}
__device__ __forceinline__ void st4(float* __restrict__ p, float4 v) {
    *reinterpret_cast<float4*>(p) = v;
}

// 7-point Laplacian on 4 consecutive z-elements at linear index i.
// z-neighbors from adjacent lanes via shuffle (16 lanes tile one z-line).
__device__ __forceinline__ float4 stencil4(const float* __restrict__ in,
                                           int i, int z0, int wi, int h,
                                           float4* cen) {
    float4 c = ld4(in + i);
    *cen = c;
    float zl = __shfl_up_sync(0xffffffffu, c.w, 1);
    float zr = __shfl_down_sync(0xffffffffu, c.x, 1);
    if (z0 == 0)  zl = 0.f;
    if (z0 == 60) zr = 0.f;
    float4 z4 = make_float4(0.f, 0.f, 0.f, 0.f);
    float4 xm = (wi > 0)      ? ld4(in + i - Zq)      : z4;
    float4 xp = (wi < Wq - 1) ? ld4(in + i + Zq)      : z4;
    float4 ym = (h  > 0)      ? ld4(in + i - Wq * Zq) : z4;
    float4 yp = (h  < Hq - 1) ? ld4(in + i + Wq * Zq) : z4;
    float4 o;
    o.x = 6.f * c.x - xm.x - xp.x - ym.x - yp.x - zl  - c.y;
    o.y = 6.f * c.y - xm.y - xp.y - ym.y - yp.y - c.x - c.z;
    o.z = 6.f * c.z - xm.z - xp.z - ym.z - yp.z - c.y - c.w;
    o.w = 6.f * c.w - xm.w - xp.w - ym.w - yp.w - c.z - zr;
    return o;
}

__device__ __forceinline__ void block_reduce_add(float val, double* target) {
    #pragma unroll
    for (int o = 16; o; o >>= 1)
        val += __shfl_xor_sync(0xffffffffu, val, o);
    __shared__ double sh[NT / 32];
    int lane = threadIdx.x & 31, wid = threadIdx.x >> 5;
    if (lane == 0) sh[wid] = (double)val;
    __syncthreads();
    if (threadIdx.x == 0) {
        double s = 0.0;
        #pragma unroll
        for (int k = 0; k < NT / 32; ++k) s += sh[k];
        atomicAdd(target, s);
    }
}

__device__ __forceinline__ void block_reduce_max(float val, unsigned* target) {
    #pragma unroll
    for (int o = 16; o; o >>= 1)
        val = fmaxf(val, __shfl_xor_sync(0xffffffffu, val, o));
    __shared__ float shm[NT / 32];
    int lane = threadIdx.x & 31, wid = threadIdx.x >> 5;
    if (lane == 0) shm[wid] = val;
    __syncthreads();
    if (threadIdx.x == 0) {
        float m = 0.f;
        #pragma unroll
        for (int k = 0; k < NT / 32; ++k) m = fmaxf(m, shm[k]);
        atomicMax(target, __float_as_uint(m));
    }
}

// REV: sweep blocks in descending order (zigzag cross-kernel L2 reuse).
template <bool REV>
__device__ __forceinline__ void decode(int& i, int& z0, int& wi,
                                       int& h, int& b) {
    int blk = REV ? (NBLK - 1 - (int)blockIdx.x) : (int)blockIdx.x;
    int tid = blk * NT + threadIdx.x;
    i  = tid * 4;
    z0 = i & 63;
    wi = (i >> 6) & 255;
    h  = (i >> 14) & 255;
    b  = i >> 22;
}

// ---------------------------------------------------------------------------
// kernels
// ---------------------------------------------------------------------------

__global__ void k_zero() {
    int t = threadIdx.x;
    if (t < (ITER + 1) * Bq) ((double*)g_rho)[t] = 0.0;
    if (t < ITER * Bq)       ((double*)g_eta)[t] = 0.0;
    if (t == 0) { g_loss = 0.0; g_max = 0u; }
}

// p0 = r0 = b - A*x0 ; rho0 += r0.r0   (ascending; r0 aliases g_p[0])
__global__ void __launch_bounds__(NT, 8)
k_init(const float* __restrict__ xin, const float* __restrict__ bin) {
    int i, z0, wi, h, b;
    decode<false>(i, z0, wi, h, b);
    float4 c;
    float4 ax = stencil4(xin, i, z0, wi, h, &c);
    float4 bb = ld4cs(bin + i);
    float4 r  = make_float4(bb.x - ax.x, bb.y - ax.y, bb.z - ax.z, bb.w - ax.w);
    st4(g_p[0] + i, r);
    float d = r.x * r.x + r.y * r.y + r.z * r.z + r.w * r.w;
    block_reduce_add(d, &g_rho[0][b]);
}

// eta kernel (descending). Pure read, no array stores.
// FIRST: eta0 = p0 . A p0
// else : beta = rho[it]/rho[it-1]; pn = r_it + beta*p_{it-1} (registers);
//        A pn = A r + beta*A p_old;  eta[it] += pn . A pn
// Scalar (FP64 divide) computed ONCE by thread 0 -> shared float.
template <bool FIRST>
__global__ void __launch_bounds__(NT, 8)
k_eta(int it) {
    int i, z0, wi, h, b;
    decode<true>(i, z0, wi, h, b);

    if (FIRST) {
        float4 c;
        float4 w = stencil4(g_p[0], i, z0, wi, h, &c);
        float d = c.x * w.x + c.y * w.y + c.z * w.z + c.w * w.w;
        block_reduce_add(d, &g_eta[0][b]);
    } else {
        __shared__ float s_beta;
        if (threadIdx.x == 0)
            s_beta = (float)(g_rho[it][b] / (g_rho[it - 1][b] + EPS));
        __syncthreads();
        float bt = s_beta;

        const float* rin = rbuf(it);
        float4 cr, cp;
        float4 wr = stencil4(rin, i, z0, wi, h, &cr);
        float4 wp = stencil4(g_p[it - 1], i, z0, wi, h, &cp);
        float4 pn = make_float4(cr.x + bt * cp.x, cr.y + bt * cp.y,
                                cr.z + bt * cp.z, cr.w + bt * cp.w);
        float4 w  = make_float4(wr.x + bt * wp.x, wr.y + bt * wp.y,
                                wr.z + bt * wp.z, wr.w + bt * wp.w);
        float d = pn.x * w.x + pn.y * w.y + pn.z * w.z + pn.w * w.w;
        block_reduce_add(d, &g_eta[it][b]);
    }
}

// update kernel (ascending). alpha = rho[it]/(eta[it]+eps)
// FIRST: r1 = p0 - alpha*A p0 -> rbuf(1). p0 already stored.
// else : pn = r_it + beta*p_{it-1}; A pn = A r + beta*A p_old (same FMAs
//        as eta, bit-identical); write g_p[it] = pn;
//        r_{it+1} = r_it - alpha*A pn -> rbuf(it+1) (no r/w hazard).
//        rho[it+1] += r_new.r_new
template <bool FIRST, bool LAST>
__global__ void __launch_bounds__(NT, 8)
k_update(int it) {
    int i, z0, wi, h, b;
    decode<false>(i, z0, wi, h, b);

    __shared__ float s_alpha, s_beta;
    if (threadIdx.x == 0) {
        s_alpha = (float)(g_rho[it][b] / (g_eta[it][b] + EPS));
        if (!FIRST)
            s_beta = (float)(g_rho[it][b] / (g_rho[it - 1][b] + EPS));
    }
    __syncthreads();
    float a = s_alpha;

    float4 r;
    if (FIRST) {
        float4 c;
        float4 w = stencil4(g_p[0], i, z0, wi, h, &c);
        r = make_float4(c.x - a * w.x, c.y - a * w.y,
                        c.z - a * w.z, c.w - a * w.w);
        st4(rbuf(1) + i, r);
    } else {
        float bt = s_beta;
        const float* rin = rbuf(it);
        float4 cr, cp;
        float4 wr = stencil4(rin, i, z0, wi, h, &cr);
        float4 wp = stencil4(g_p[it - 1], i, z0, wi, h, &cp);
        float4 pn = make_float4(cr.x + bt * cp.x, cr.y + bt * cp.y,
                                cr.z + bt * cp.z, cr.w + bt * cp.w);
        float4 w  = make_float4(wr.x + bt * wp.x, wr.y + bt * wp.y,
                                wr.z + bt * wp.z, wr.w + bt * wp.w);
        st4(g_p[it] + i, pn);
        r = make_float4(cr.x - a * w.x, cr.y - a * w.y,
                        cr.z - a * w.z, cr.w - a * w.w);
        if (!LAST) st4(rbuf(it + 1) + i, r);
    }
    float d = r.x * r.x + r.y * r.y + r.z * r.z + r.w * r.w;
    block_reduce_add(d, &g_rho[it + 1][b]);
}

// final (descending): x = x0 + sum_k alpha_k p_k ; out, loss, max_error
// All 8 alphas computed once by thread 0 into shared.
__global__ void __launch_bounds__(NT, 8)
k_final(const float* __restrict__ xin, const float* __restrict__ ref,
        float* __restrict__ out) {
    int i, z0, wi, h, b;
    decode<true>(i, z0, wi, h, b);

    __shared__ float s_alpha[ITER];
    if (threadIdx.x < ITER)
        s_alpha[threadIdx.x] =
            (float)(g_rho[threadIdx.x][b] / (g_eta[threadIdx.x][b] + EPS));
    __syncthreads();

    float4 x = ld4cs(xin + i);
    #pragma unroll
    for (int k = 0; k < ITER; ++k) {
        float a = s_alpha[k];
        float4 pk = ld4cs(g_p[k] + i);
        x.x += a * pk.x; x.y += a * pk.y;
        x.z += a * pk.z; x.w += a * pk.w;
    }
    __stcs(out + 1 + i + 0, x.x);
    __stcs(out + 1 + i + 1, x.y);
    __stcs(out + 1 + i + 2, x.z);
    __stcs(out + 1 + i + 3, x.w);

    float4 rf = ld4cs(ref + i);
    float dx = x.x - rf.x, dy = x.y - rf.y;
    float dz = x.z - rf.z, dw = x.w - rf.w;
    float ss = dx * dx + dy * dy + dz * dz + dw * dw;
    float mx = fmaxf(fmaxf(fabsf(dx), fabsf(dy)),
                     fmaxf(fabsf(dz), fabsf(dw)));
    block_reduce_add(ss, &g_loss);
    block_reduce_max(mx, &g_max);
}

__global__ void k_writeout(float* __restrict__ out) {
    out[0] = (float)(g_loss / (double)N);
    out[N + 1] = __uint_as_float(g_max);
    double s = 0.0;
    #pragma unroll
    for (int b = 0; b < Bq; ++b) s += g_rho[ITER][b];
    out[N + 2] = (float)(s / (double)Bq);
}

// ---------------------------------------------------------------------------

extern "C" void kernel_launch(void* const* d_in, const int* in_sizes, int n_in,
                              void* d_out, int out_size) {
    const float* x   = (const float*)d_in[0];
    const float* b   = (const float*)d_in[1];
    const float* ref = (const float*)d_in[2];
    float* out = (float*)d_out;

    k_zero<<<1, 64>>>();
    k_init<<<NBLK, NT>>>(x, b);

    k_eta<true><<<NBLK, NT>>>(0);
    k_update<true, false><<<NBLK, NT>>>(0);

    for (int it = 1; it < ITER - 1; ++it) {
        k_eta<false><<<NBLK, NT>>>(it);
        k_update<false, false><<<NBLK, NT>>>(it);
    }

    k_eta<false><<<NBLK, NT>>>(ITER - 1);
    k_update<false, true><<<NBLK, NT>>>(ITER - 1);

    k_final<<<NBLK, NT>>>(x, ref, out);
    k_writeout<<<1, 1>>>(out);
}

// round 8
// speedup vs baseline: 3.1237x; 1.1617x over previous
#include <cuda_runtime.h>

// Problem constants
#define Bq 4
#define Hq 256
#define Wq 256
#define Zq 64
#define ITER 8
#define EPS 1e-6

constexpr int N     = Bq * Hq * Wq * Zq;  // 16,777,216
#define NT 256
constexpr int NBLK4 = N / 4 / NT;         // 16384 blocks (4 elem/thread)
constexpr int NBLK8 = N / 8 / NT;         // 8192  blocks (8 elem/thread)

// Scratch (device globals: allocation is forbidden)
__device__ float g_x[N];
__device__ float g_r[N];
__device__ float g_pa[N];   // ping-pong p buffers
__device__ float g_pb[N];

__device__ double   g_rho[ITER + 1][Bq];
__device__ double   g_eta[ITER][Bq];
__device__ double   g_loss;
__device__ unsigned g_max;

// ---------------------------------------------------------------------------
// helpers
// ---------------------------------------------------------------------------

__device__ __forceinline__ float4 ld4(const float* __restrict__ p) {
    return *reinterpret_cast<const float4*>(p);
}
__device__ __forceinline__ float4 ld4cs(const float* __restrict__ p) {
    return __ldcs(reinterpret_cast<const float4*>(p));
}
__device__ __forceinline__ void st4(float* __restrict__ p, float4 v) {
    *reinterpret_cast<float4*>(p) = v;
}
__device__ __forceinline__ void st4cs(float* __restrict__ p, float4 v) {
    __stcs(reinterpret_cast<float4*>(p), v);
}

// 4-elem stencil (z-neighbors via lane shuffle; 16 lanes per z-line).
__device__ __forceinline__ float4 stencil4(const float* __restrict__ in,
                                           int i, int z0, int wi, int h,
                                           float4* cen) {
    float4 c = ld4(in + i);
    *cen = c;
    float zl = __shfl_up_sync(0xffffffffu, c.w, 1);
    float zr = __shfl_down_sync(0xffffffffu, c.x, 1);
    if (z0 == 0)  zl = 0.f;
    if (z0 == 60) zr = 0.f;
    float4 z4 = make_float4(0.f, 0.f, 0.f, 0.f);
    float4 xm = (wi > 0)      ? ld4(in + i - Zq)      : z4;
    float4 xp = (wi < Wq - 1) ? ld4(in + i + Zq)      : z4;
    float4 ym = (h  > 0)      ? ld4(in + i - Wq * Zq) : z4;
    float4 yp = (h  < Hq - 1) ? ld4(in + i + Wq * Zq) : z4;
    float4 o;
    o.x = 6.f * c.x - xm.x - xp.x - ym.x - yp.x - zl  - c.y;
    o.y = 6.f * c.y - xm.y - xp.y - ym.y - yp.y - c.x - c.z;
    o.z = 6.f * c.z - xm.z - xp.z - ym.z - yp.z - c.y - c.w;
    o.w = 6.f * c.w - xm.w - xp.w - ym.w - yp.w - c.z - zr;
    return o;
}

// 8-elem stencil (8 lanes per z-line; z0 in {0,8,...,56}).
__device__ __forceinline__ void stencil8(const float* __restrict__ in,
                                         int i, int z0, int wi, int h,
                                         float4& c0, float4& c1,
                                         float4& o0, float4& o1) {
    c0 = ld4(in + i);
    c1 = ld4(in + i + 4);
    float zl = __shfl_up_sync(0xffffffffu, c1.w, 1);
    float zr = __shfl_down_sync(0xffffffffu, c0.x, 1);
    if (z0 == 0)  zl = 0.f;
    if (z0 == 56) zr = 0.f;
    float4 z4 = make_float4(0.f, 0.f, 0.f, 0.f);
    bool wm = wi > 0, wp = wi < Wq - 1, hm = h > 0, hp = h < Hq - 1;
    float4 xm0 = wm ? ld4(in + i - Zq)          : z4;
    float4 xm1 = wm ? ld4(in + i + 4 - Zq)      : z4;
    float4 xp0 = wp ? ld4(in + i + Zq)          : z4;
    float4 xp1 = wp ? ld4(in + i + 4 + Zq)      : z4;
    float4 ym0 = hm ? ld4(in + i - Wq * Zq)     : z4;
    float4 ym1 = hm ? ld4(in + i + 4 - Wq * Zq) : z4;
    float4 yp0 = hp ? ld4(in + i + Wq * Zq)     : z4;
    float4 yp1 = hp ? ld4(in + i + 4 + Wq * Zq) : z4;
    o0.x = 6.f * c0.x - xm0.x - xp0.x - ym0.x - yp0.x - zl   - c0.y;
    o0.y = 6.f * c0.y - xm0.y - xp0.y - ym0.y - yp0.y - c0.x - c0.z;
    o0.z = 6.f * c0.z - xm0.z - xp0.z - ym0.z - yp0.z - c0.y - c0.w;
    o0.w = 6.f * c0.w - xm0.w - xp0.w - ym0.w - yp0.w - c0.z - c1.x;
    o1.x = 6.f * c1.x - xm1.x - xp1.x - ym1.x - yp1.x - c0.w - c1.y;
    o1.y = 6.f * c1.y - xm1.y - xp1.y - ym1.y - yp1.y - c1.x - c1.z;
    o1.z = 6.f * c1.z - xm1.z - xp1.z - ym1.z - yp1.z - c1.y - c1.w;
    o1.w = 6.f * c1.w - xm1.w - xp1.w - ym1.w - yp1.w - c1.z - zr;
}

__device__ __forceinline__ void block_reduce_add(float val, double* target) {
    #pragma unroll
    for (int o = 16; o; o >>= 1)
        val += __shfl_xor_sync(0xffffffffu, val, o);
    __shared__ double sh[NT / 32];
    int lane = threadIdx.x & 31, wid = threadIdx.x >> 5;
    if (lane == 0) sh[wid] = (double)val;
    __syncthreads();
    if (threadIdx.x == 0) {
        double s = 0.0;
        #pragma unroll
        for (int k = 0; k < NT / 32; ++k) s += sh[k];
        atomicAdd(target, s);
    }
}

__device__ __forceinline__ void block_reduce_max(float val, unsigned* target) {
    #pragma unroll
    for (int o = 16; o; o >>= 1)
        val = fmaxf(val, __shfl_xor_sync(0xffffffffu, val, o));
    __shared__ float shm[NT / 32];
    int lane = threadIdx.x & 31, wid = threadIdx.x >> 5;
    if (lane == 0) shm[wid] = val;
    __syncthreads();
    if (threadIdx.x == 0) {
        float m = 0.f;
        #pragma unroll
        for (int k = 0; k < NT / 32; ++k) m = fmaxf(m, shm[k]);
        atomicMax(target, __float_as_uint(m));
    }
}

// REV: descending block sweep (zigzag cross-kernel L2 reuse).
template <bool REV>
__device__ __forceinline__ void decode4(int& i, int& z0, int& wi,
                                        int& h, int& b) {
    int blk = REV ? (NBLK4 - 1 - (int)blockIdx.x) : (int)blockIdx.x;
    int tid = blk * NT + threadIdx.x;
    i  = tid * 4;
    z0 = i & 63;
    wi = (i >> 6) & 255;
    h  = (i >> 14) & 255;
    b  = i >> 22;
}

template <bool REV>
__device__ __forceinline__ void decode8(int& i, int& z0, int& wi,
                                        int& h, int& b) {
    int blk = REV ? (NBLK8 - 1 - (int)blockIdx.x) : (int)blockIdx.x;
    int tid = blk * NT + threadIdx.x;
    i  = tid * 8;
    z0 = i & 63;
    wi = (i >> 6) & 255;
    h  = (i >> 14) & 255;
    b  = i >> 22;
}

__device__ __forceinline__ float* pbuf(int it) {
    return (it & 1) ? g_pb : g_pa;
}

// ---------------------------------------------------------------------------
// kernels
// ---------------------------------------------------------------------------

__global__ void k_zero() {
    int t = threadIdx.x;
    if (t < (ITER + 1) * Bq) ((double*)g_rho)[t] = 0.0;
    if (t < ITER * Bq)       ((double*)g_eta)[t] = 0.0;
    if (t == 0) { g_loss = 0.0; g_max = 0u; }
}

// r = b - A*x0 ; p0 = r ; rho0 += r.r   (ascending, 8 elem/thread)
__global__ void __launch_bounds__(NT, 5)
k_init(const float* __restrict__ xin, const float* __restrict__ bin) {
    int i, z0, wi, h, b;
    decode8<false>(i, z0, wi, h, b);
    float4 c0, c1, a0, a1;
    stencil8(xin, i, z0, wi, h, c0, c1, a0, a1);
    float4 b0 = ld4cs(bin + i), b1 = ld4cs(bin + i + 4);
    float4 r0 = make_float4(b0.x - a0.x, b0.y - a0.y, b0.z - a0.z, b0.w - a0.w);
    float4 r1 = make_float4(b1.x - a1.x, b1.y - a1.y, b1.z - a1.z, b1.w - a1.w);
    st4(g_r + i, r0);      st4(g_r + i + 4, r1);
    st4(g_pa + i, r0);     st4(g_pa + i + 4, r1);
    float d = r0.x * r0.x + r0.y * r0.y + r0.z * r0.z + r0.w * r0.w
            + r1.x * r1.x + r1.y * r1.y + r1.z * r1.z + r1.w * r1.w;
    block_reduce_add(d, &g_rho[0][b]);
}

// eta kernel (descending, 4 elem/thread — double stencil, reg-heavy).
// FIRST: eta0 = p0 . A p0
// else : beta = rho[it]/rho[it-1]; p_new = r + beta*p_old -> pbuf(it);
//        A p_new = A r + beta*A p_old;  eta[it] += p_new . A p_new
template <bool FIRST>
__global__ void __launch_bounds__(NT, 8)
k_eta(int it) {
    int i, z0, wi, h, b;
    decode4<true>(i, z0, wi, h, b);

    if (FIRST) {
        float4 c;
        float4 w = stencil4(g_pa, i, z0, wi, h, &c);
        float d = c.x * w.x + c.y * w.y + c.z * w.z + c.w * w.w;
        block_reduce_add(d, &g_eta[0][b]);
    } else {
        __shared__ float s_beta;
        if (threadIdx.x == 0)
            s_beta = (float)(g_rho[it][b] / (g_rho[it - 1][b] + EPS));
        __syncthreads();
        float bt = s_beta;

        const float* pold = pbuf(it - 1);
        float* pnew = pbuf(it);
        float4 cr, cp;
        float4 wr = stencil4(g_r, i, z0, wi, h, &cr);
        float4 wp = stencil4(pold, i, z0, wi, h, &cp);
        float4 pn = make_float4(cr.x + bt * cp.x, cr.y + bt * cp.y,
                                cr.z + bt * cp.z, cr.w + bt * cp.w);
        float4 w  = make_float4(wr.x + bt * wp.x, wr.y + bt * wp.y,
                                wr.z + bt * wp.z, wr.w + bt * wp.w);
        st4(pnew + i, pn);
        float d = pn.x * w.x + pn.y * w.y + pn.z * w.z + pn.w * w.w;
        block_reduce_add(d, &g_eta[it][b]);
    }
}

// update kernel (ascending, 8 elem/thread). alpha = rho[it]/(eta[it]+eps)
//   w = A p (single stencil); r -= alpha*w; x += alpha*p; rho[it+1] += r.r
//   LAST: x -> out[1..N] fused with loss/max_error vs ref; r,x not stored.
template <bool FIRST, bool LAST>
__global__ void __launch_bounds__(NT, 5)
k_update(int it, const float* __restrict__ xin,
         const float* __restrict__ ref, float* __restrict__ out) {
    int i, z0, wi, h, b;
    decode8<false>(i, z0, wi, h, b);

    __shared__ float s_alpha;
    if (threadIdx.x == 0)
        s_alpha = (float)(g_rho[it][b] / (g_eta[it][b] + EPS));
    __syncthreads();
    float a = s_alpha;

    const float* p = pbuf(it);
    float4 cp0, cp1, w0, w1;
    stencil8(p, i, z0, wi, h, cp0, cp1, w0, w1);
    float4 r0 = ld4(g_r + i), r1 = ld4(g_r + i + 4);
    r0.x -= a * w0.x; r0.y -= a * w0.y; r0.z -= a * w0.z; r0.w -= a * w0.w;
    r1.x -= a * w1.x; r1.y -= a * w1.y; r1.z -= a * w1.z; r1.w -= a * w1.w;

    float4 x0 = FIRST ? ld4cs(xin + i)     : ld4cs(g_x + i);
    float4 x1 = FIRST ? ld4cs(xin + i + 4) : ld4cs(g_x + i + 4);
    x0.x += a * cp0.x; x0.y += a * cp0.y; x0.z += a * cp0.z; x0.w += a * cp0.w;
    x1.x += a * cp1.x; x1.y += a * cp1.y; x1.z += a * cp1.z; x1.w += a * cp1.w;

    if (!LAST) {
        st4(g_r + i, r0);      st4(g_r + i + 4, r1);
        st4cs(g_x + i, x0);    st4cs(g_x + i + 4, x1);
    } else {
        __stcs(out + 1 + i + 0, x0.x);
        __stcs(out + 1 + i + 1, x0.y);
        __stcs(out + 1 + i + 2, x0.z);
        __stcs(out + 1 + i + 3, x0.w);
        __stcs(out + 1 + i + 4, x1.x);
        __stcs(out + 1 + i + 5, x1.y);
        __stcs(out + 1 + i + 6, x1.z);
        __stcs(out + 1 + i + 7, x1.w);
        float4 f0 = ld4cs(ref + i), f1 = ld4cs(ref + i + 4);
        float dx0 = x0.x - f0.x, dy0 = x0.y - f0.y;
        float dz0 = x0.z - f0.z, dw0 = x0.w - f0.w;
        float dx1 = x1.x - f1.x, dy1 = x1.y - f1.y;
        float dz1 = x1.z - f1.z, dw1 = x1.w - f1.w;
        float ss = dx0 * dx0 + dy0 * dy0 + dz0 * dz0 + dw0 * dw0
                 + dx1 * dx1 + dy1 * dy1 + dz1 * dz1 + dw1 * dw1;
        float mx = fmaxf(fmaxf(fmaxf(fabsf(dx0), fabsf(dy0)),
                               fmaxf(fabsf(dz0), fabsf(dw0))),
                         fmaxf(fmaxf(fabsf(dx1), fabsf(dy1)),
                               fmaxf(fabsf(dz1), fabsf(dw1))));
        block_reduce_add(ss, &g_loss);
        block_reduce_max(mx, &g_max);
    }
    float d = r0.x * r0.x + r0.y * r0.y + r0.z * r0.z + r0.w * r0.w
            + r1.x * r1.x + r1.y * r1.y + r1.z * r1.z + r1.w * r1.w;
    block_reduce_add(d, &g_rho[it + 1][b]);
}

__global__ void k_writeout(float* __restrict__ out) {
    out[0] = (float)(g_loss / (double)N);
    out[N + 1] = __uint_as_float(g_max);
    double s = 0.0;
    #pragma unroll
    for (int b = 0; b < Bq; ++b) s += g_rho[ITER][b];
    out[N + 2] = (float)(s / (double)Bq);
}

// ---------------------------------------------------------------------------

extern "C" void kernel_launch(void* const* d_in, const int* in_sizes, int n_in,
                              void* d_out, int out_size) {
    const float* x   = (const float*)d_in[0];
    const float* b   = (const float*)d_in[1];
    const float* ref = (const float*)d_in[2];
    float* out = (float*)d_out;

    k_zero<<<1, 64>>>();
    k_init<<<NBLK8, NT>>>(x, b);

    k_eta<true><<<NBLK4, NT>>>(0);
    k_update<true, false><<<NBLK8, NT>>>(0, x, nullptr, nullptr);

    for (int it = 1; it < ITER - 1; ++it) {
        k_eta<false><<<NBLK4, NT>>>(it);
        k_update<false, false><<<NBLK8, NT>>>(it, nullptr, nullptr, nullptr);
    }

    k_eta<false><<<NBLK4, NT>>>(ITER - 1);
    k_update<false, true><<<NBLK8, NT>>>(ITER - 1, nullptr, ref, out);

    k_writeout<<<1, 1>>>(out);
}

// round 9
// speedup vs baseline: 3.8208x; 1.2231x over previous
#include <cuda_runtime.h>

// Problem constants
#define Bq 4
#define Hq 256
#define Wq 256
#define Zq 64
#define ITER 8
#define EPS 1e-6

constexpr int N    = Bq * Hq * Wq * Zq;   // 16,777,216
constexpr int SAMP = Hq * Wq * Zq;        // 4,194,304
#define NT 256
constexpr int GRID = 1184;                // 148 SMs x 8 blocks (co-resident)
constexpr int SBLK = GRID / Bq;           // 296 blocks per sample
constexpr int TPS  = SAMP / (NT * 4);     // 4096 tiles (of 1024 elems) per sample

// Scratch (device globals: allocation is forbidden).
// Buffer versioning: each r_k / p_k written exactly once, read only after ->
// no stale-L1 hazard across phases of the persistent kernel.
__device__ float g_p[ITER][N];        // p_0..p_7
__device__ float g_r[ITER][N];        // slot k holds r_k (slot 0 unused; r0==p0)

__device__ double   g_rho[ITER + 1][Bq];
__device__ double   g_eta[ITER][Bq];
__device__ double   g_loss;
__device__ unsigned g_max;

// grid barrier state (monotonic gen across graph replays; count self-resets)
__device__ unsigned g_bar_count;
__device__ unsigned g_bar_gen;

// ---------------------------------------------------------------------------
// helpers
// ---------------------------------------------------------------------------

__device__ __forceinline__ float4 ld4(const float* __restrict__ p) {
    return *reinterpret_cast<const float4*>(p);
}
__device__ __forceinline__ float4 ld4cs(const float* __restrict__ p) {
    return __ldcs(reinterpret_cast<const float4*>(p));
}
__device__ __forceinline__ void st4(float* __restrict__ p, float4 v) {
    *reinterpret_cast<float4*>(p) = v;
}

// 7-point Laplacian on 4 consecutive z-elems; z-neighbors via lane shuffle
// (16 lanes tile one z-line; boundaries coincide with z0 masks).
__device__ __forceinline__ float4 stencil4(const float* __restrict__ in,
                                           int i, int z0, int wi, int h,
                                           float4* cen) {
    float4 c = ld4(in + i);
    *cen = c;
    float zl = __shfl_up_sync(0xffffffffu, c.w, 1);
    float zr = __shfl_down_sync(0xffffffffu, c.x, 1);
    if (z0 == 0)  zl = 0.f;
    if (z0 == 60) zr = 0.f;
    float4 z4 = make_float4(0.f, 0.f, 0.f, 0.f);
    float4 xm = (wi > 0)      ? ld4(in + i - Zq)      : z4;
    float4 xp = (wi < Wq - 1) ? ld4(in + i + Zq)      : z4;
    float4 ym = (h  > 0)      ? ld4(in + i - Wq * Zq) : z4;
    float4 yp = (h  < Hq - 1) ? ld4(in + i + Wq * Zq) : z4;
    float4 o;
    o.x = 6.f * c.x - xm.x - xp.x - ym.x - yp.x - zl  - c.y;
    o.y = 6.f * c.y - xm.y - xp.y - ym.y - yp.y - c.x - c.z;
    o.z = 6.f * c.z - xm.z - xp.z - ym.z - yp.z - c.y - c.w;
    o.w = 6.f * c.w - xm.w - xp.w - ym.w - yp.w - c.z - zr;
    return o;
}

__device__ __forceinline__ void block_reduce_add(float val, double* target) {
    __syncthreads();                       // protect shared reuse across calls
    #pragma unroll
    for (int o = 16; o; o >>= 1)
        val += __shfl_xor_sync(0xffffffffu, val, o);
    __shared__ double sh[NT / 32];
    int lane = threadIdx.x & 31, wid = threadIdx.x >> 5;
    if (lane == 0) sh[wid] = (double)val;
    __syncthreads();
    if (threadIdx.x == 0) {
        double s = 0.0;
        #pragma unroll
        for (int k = 0; k < NT / 32; ++k) s += sh[k];
        atomicAdd(target, s);
    }
}

__device__ __forceinline__ void block_reduce_max(float val, unsigned* target) {
    __syncthreads();
    #pragma unroll
    for (int o = 16; o; o >>= 1)
        val = fmaxf(val, __shfl_xor_sync(0xffffffffu, val, o));
    __shared__ float shm[NT / 32];
    int lane = threadIdx.x & 31, wid = threadIdx.x >> 5;
    if (lane == 0) shm[wid] = val;
    __syncthreads();
    if (threadIdx.x == 0) {
        float m = 0.f;
        #pragma unroll
        for (int k = 0; k < NT / 32; ++k) m = fmaxf(m, shm[k]);
        atomicMax(target, __float_as_uint(m));
    }
}

// software grid barrier (all GRID blocks resident by construction)
__device__ __forceinline__ void grid_sync() {
    __syncthreads();
    if (threadIdx.x == 0) {
        unsigned my = *(volatile unsigned*)&g_bar_gen;   // read BEFORE arrive
        __threadfence();                                 // publish my writes
        if (atomicAdd(&g_bar_count, 1) == GRID - 1) {
            g_bar_count = 0;
            __threadfence();
            atomicAdd(&g_bar_gen, 1);
        } else {
            while (*(volatile unsigned*)&g_bar_gen == my) __nanosleep(64);
        }
        __threadfence();
    }
    __syncthreads();
}

// element decode for sample-tile t (0..TPS-1) of sample sb
__device__ __forceinline__ void decode(int sb, int t, int& i, int& z0,
                                       int& wi, int& h) {
    i  = (sb << 22) + (t * NT + (int)threadIdx.x) * 4;
    z0 = i & 63;
    wi = (i >> 6) & 255;
    h  = (i >> 14) & 255;
}

__device__ __forceinline__ float ldscal(const double* num, const double* den) {
    return (float)(__ldcg(num) / (__ldcg(den) + EPS));
}

// ---------------------------------------------------------------------------
// kernels
// ---------------------------------------------------------------------------

__global__ void k_zero() {
    int t = threadIdx.x;
    if (t < (ITER + 1) * Bq) ((double*)g_rho)[t] = 0.0;
    if (t < ITER * Bq)       ((double*)g_eta)[t] = 0.0;
    if (t == 0) { g_loss = 0.0; g_max = 0u; }
}

__global__ void __launch_bounds__(NT, 8)
k_cg(const float* __restrict__ x0, const float* __restrict__ bin,
     const float* __restrict__ ref, float* __restrict__ out) {
    const int sb   = blockIdx.x & 3;        // sample
    const int sblk = blockIdx.x >> 2;       // 0..SBLK-1
    __shared__ float s_a, s_b;

    // ---- P0: p0 = r0 = b - A x0 ; rho0 ----
    {
        float acc = 0.f;
        for (int t = sblk; t < TPS; t += SBLK) {
            int i, z0, wi, h; decode(sb, t, i, z0, wi, h);
            float4 c;
            float4 ax = stencil4(x0, i, z0, wi, h, &c);
            float4 bb = ld4cs(bin + i);
            float4 r  = make_float4(bb.x - ax.x, bb.y - ax.y,
                                    bb.z - ax.z, bb.w - ax.w);
            st4(g_p[0] + i, r);
            acc += r.x * r.x + r.y * r.y + r.z * r.z + r.w * r.w;
        }
        block_reduce_add(acc, &g_rho[0][sb]);
    }
    grid_sync();

    // ---- P1: eta0 = p0 . A p0 ----
    {
        float acc = 0.f;
        for (int t = sblk; t < TPS; t += SBLK) {
            int tt = TPS - 1 - t;           // zigzag
            int i, z0, wi, h; decode(sb, tt, i, z0, wi, h);
            float4 c;
            float4 w = stencil4(g_p[0], i, z0, wi, h, &c);
            acc += c.x * w.x + c.y * w.y + c.z * w.z + c.w * w.w;
        }
        block_reduce_add(acc, &g_eta[0][sb]);
    }
    grid_sync();

    // ---- P2: r1 = p0 - alpha0 * A p0 ; rho1 ----
    {
        if (threadIdx.x == 0) s_a = ldscal(&g_rho[0][sb], &g_eta[0][sb]);
        __syncthreads();
        float a = s_a;
        float acc = 0.f;
        for (int t = sblk; t < TPS; t += SBLK) {
            int i, z0, wi, h; decode(sb, t, i, z0, wi, h);
            float4 c;
            float4 w = stencil4(g_p[0], i, z0, wi, h, &c);
            float4 r = make_float4(c.x - a * w.x, c.y - a * w.y,
                                   c.z - a * w.z, c.w - a * w.w);
            st4(g_r[1] + i, r);
            acc += r.x * r.x + r.y * r.y + r.z * r.z + r.w * r.w;
        }
        block_reduce_add(acc, &g_rho[1][sb]);
    }
    grid_sync();

    for (int k = 1; k < ITER; ++k) {
        // ---- eta_k: p_k = r_k + beta*p_{k-1} (store);
        //      A p_k = A r_k + beta*A p_{k-1}; eta_k = p_k . A p_k ----
        {
            if (threadIdx.x == 0)
                s_b = (float)(__ldcg(&g_rho[k][sb]) /
                              (__ldcg(&g_rho[k - 1][sb]) + EPS));
            __syncthreads();
            float bt = s_b;
            const float* rk = g_r[k];
            const float* po = g_p[k - 1];
            float* pn = g_p[k];
            float acc = 0.f;
            for (int t = sblk; t < TPS; t += SBLK) {
                int tt = TPS - 1 - t;       // zigzag
                int i, z0, wi, h; decode(sb, tt, i, z0, wi, h);
                float4 cr, cp;
                float4 wr = stencil4(rk, i, z0, wi, h, &cr);
                float4 wp = stencil4(po, i, z0, wi, h, &cp);
                float4 p4 = make_float4(cr.x + bt * cp.x, cr.y + bt * cp.y,
                                        cr.z + bt * cp.z, cr.w + bt * cp.w);
                float4 w4 = make_float4(wr.x + bt * wp.x, wr.y + bt * wp.y,
                                        wr.z + bt * wp.z, wr.w + bt * wp.w);
                st4(pn + i, p4);
                acc += p4.x * w4.x + p4.y * w4.y + p4.z * w4.z + p4.w * w4.w;
            }
            block_reduce_add(acc, &g_eta[k][sb]);
        }
        grid_sync();

        if (k < ITER - 1) {
            // ---- upd_k: r_{k+1} = r_k - alpha_k * A p_k ; rho_{k+1} ----
            if (threadIdx.x == 0) s_a = ldscal(&g_rho[k][sb], &g_eta[k][sb]);
            __syncthreads();
            float a = s_a;
            const float* pk = g_p[k];
            const float* rk = g_r[k];
            float* rn = g_r[k + 1];
            float acc = 0.f;
            for (int t = sblk; t < TPS; t += SBLK) {
                int i, z0, wi, h; decode(sb, t, i, z0, wi, h);
                float4 cp;
                float4 w = stencil4(pk, i, z0, wi, h, &cp);
                float4 r = ld4(rk + i);
                r.x -= a * w.x; r.y -= a * w.y;
                r.z -= a * w.z; r.w -= a * w.w;
                st4(rn + i, r);
                acc += r.x * r.x + r.y * r.y + r.z * r.z + r.w * r.w;
            }
            block_reduce_add(acc, &g_rho[k + 1][sb]);
            grid_sync();
        }
    }

    // ---- merged last phase: rho8 dot + x = x0 + sum alpha_k p_k + outputs ----
    {
        __shared__ float s_alpha[ITER];
        if (threadIdx.x < ITER)
            s_alpha[threadIdx.x] =
                ldscal(&g_rho[threadIdx.x][sb], &g_eta[threadIdx.x][sb]);
        __syncthreads();

        float accr = 0.f, accl = 0.f, mx = 0.f;
        const float a7 = s_alpha[ITER - 1];
        for (int t = sblk; t < TPS; t += SBLK) {
            int i, z0, wi, h; decode(sb, t, i, z0, wi, h);
            float4 cp7;
            float4 w  = stencil4(g_p[ITER - 1], i, z0, wi, h, &cp7);
            float4 r7 = ld4(g_r[ITER - 1] + i);
            float4 r8 = make_float4(r7.x - a7 * w.x, r7.y - a7 * w.y,
                                    r7.z - a7 * w.z, r7.w - a7 * w.w);
            accr += r8.x * r8.x + r8.y * r8.y + r8.z * r8.z + r8.w * r8.w;

            float4 x = ld4cs(x0 + i);
            #pragma unroll
            for (int k = 0; k < ITER - 1; ++k) {
                float a = s_alpha[k];
                float4 pk = ld4cs(g_p[k] + i);
                x.x += a * pk.x; x.y += a * pk.y;
                x.z += a * pk.z; x.w += a * pk.w;
            }
            x.x += a7 * cp7.x; x.y += a7 * cp7.y;
            x.z += a7 * cp7.z; x.w += a7 * cp7.w;

            __stcs(out + 1 + i + 0, x.x);
            __stcs(out + 1 + i + 1, x.y);
            __stcs(out + 1 + i + 2, x.z);
            __stcs(out + 1 + i + 3, x.w);

            float4 rf = ld4cs(ref + i);
            float dx = x.x - rf.x, dy = x.y - rf.y;
            float dz = x.z - rf.z, dw = x.w - rf.w;
            accl += dx * dx + dy * dy + dz * dz + dw * dw;
            mx = fmaxf(mx, fmaxf(fmaxf(fabsf(dx), fabsf(dy)),
                                 fmaxf(fabsf(dz), fabsf(dw))));
        }
        block_reduce_add(accr, &g_rho[ITER][sb]);
        block_reduce_max(mx, &g_max);
        block_reduce_add(accl, &g_loss);
    }
}

__global__ void k_writeout(float* __restrict__ out) {
    out[0] = (float)(g_loss / (double)N);
    out[N + 1] = __uint_as_float(g_max);
    double s = 0.0;
    #pragma unroll
    for (int b = 0; b < Bq; ++b) s += g_rho[ITER][b];
    out[N + 2] = (float)(s / (double)Bq);
}

// ---------------------------------------------------------------------------

extern "C" void kernel_launch(void* const* d_in, const int* in_sizes, int n_in,
                              void* d_out, int out_size) {
    const float* x   = (const float*)d_in[0];
    const float* b   = (const float*)d_in[1];
    const float* ref = (const float*)d_in[2];
    float* out = (float*)d_out;

    k_zero<<<1, 64>>>();
    k_cg<<<GRID, NT>>>(x, b, ref, out);
    k_writeout<<<1, 1>>>(out);
}

// round 10
// speedup vs baseline: 4.5918x; 1.2018x over previous
#include <cuda_runtime.h>

// Problem constants
#define Bq 4
#define Hq 256
#define Wq 256
#define Zq 64
#define ITER 8
#define EPS 1e-6

constexpr int N    = Bq * Hq * Wq * Zq;   // 16,777,216
constexpr int SAMP = Hq * Wq * Zq;        // 4,194,304
#define NT 256
constexpr int GRID = 592;                 // 148 SMs x 4 blocks co-resident
constexpr int SBLK = GRID / Bq;           // 148 blocks per sample
constexpr int TPS  = SAMP / (NT * 4);     // 4096 tiles per sample
constexpr int WZ   = Wq * Zq;

// Scratch (device globals; allocation forbidden). Write-once buffer
// versioning -> no stale-L1 hazard inside the persistent kernel.
__device__ float g_p[ITER][N];   // p_0..p_7
__device__ float g_r[ITER][N];   // slot k holds r_k (slot 0 unused; r0==p0)

__device__ double   g_rho[ITER + 1][Bq];  // DIRECT dots r_k.r_k
__device__ double   g_eta[ITER][Bq];      // p_k . w_k
__device__ double   g_tau[ITER][Bq];      // r_k . w_k
__device__ double   g_om [ITER][Bq];      // w_k . w_k
__device__ double   g_loss;
__device__ unsigned g_max;

__device__ unsigned g_bar_count;          // self-resetting
__device__ unsigned g_bar_gen;            // monotonic across replays

// ---------------------------------------------------------------------------
// helpers
// ---------------------------------------------------------------------------

__device__ __forceinline__ float4 ld4(const float* __restrict__ p) {
    return *reinterpret_cast<const float4*>(p);
}
__device__ __forceinline__ float4 ld4cs(const float* __restrict__ p) {
    return __ldcs(reinterpret_cast<const float4*>(p));
}
__device__ __forceinline__ void st4(float* __restrict__ p, float4 v) {
    *reinterpret_cast<float4*>(p) = v;
}
__device__ __forceinline__ float dot4(float4 a, float4 b) {
    return a.x * b.x + a.y * b.y + a.z * b.z + a.w * b.w;
}

// 7-pt Laplacian of quad c given 4 side quads; z-neighbors via lane shuffle
// (16 lanes tile one z-line; lane-boundary shuffles are exactly the z-edge
// masks, so cross-column contamination at lanes 15/16 is masked out).
// MUST be called unconditionally by all lanes (shuffles inside).
__device__ __forceinline__ float4 lap(float4 c, float4 xm, float4 xp,
                                      float4 ym, float4 yp, int z0) {
    float zl = __shfl_up_sync(0xffffffffu, c.w, 1);
    float zr = __shfl_down_sync(0xffffffffu, c.x, 1);
    if (z0 == 0)  zl = 0.f;
    if (z0 == 60) zr = 0.f;
    float4 o;
    o.x = 6.f * c.x - xm.x - xp.x - ym.x - yp.x - zl  - c.y;
    o.y = 6.f * c.y - xm.y - xp.y - ym.y - yp.y - c.x - c.z;
    o.z = 6.f * c.z - xm.z - xp.z - ym.z - yp.z - c.y - c.w;
    o.w = 6.f * c.w - xm.w - xp.w - ym.w - yp.w - c.z - zr;
    return o;
}

__device__ __forceinline__ void block_reduce_add(float val, double* target) {
    __syncthreads();
    #pragma unroll
    for (int o = 16; o; o >>= 1)
        val += __shfl_xor_sync(0xffffffffu, val, o);
    __shared__ double sh[NT / 32];
    int lane = threadIdx.x & 31, wid = threadIdx.x >> 5;
    if (lane == 0) sh[wid] = (double)val;
    __syncthreads();
    if (threadIdx.x == 0) {
        double s = 0.0;
        #pragma unroll
        for (int k = 0; k < NT / 32; ++k) s += sh[k];
        atomicAdd(target, s);
    }
}

__device__ __forceinline__ void block_reduce4(float v0, float v1, float v2,
                                              float v3, double* t0, double* t1,
                                              double* t2, double* t3) {
    __syncthreads();
    #pragma unroll
    for (int o = 16; o; o >>= 1) {
        v0 += __shfl_xor_sync(0xffffffffu, v0, o);
        v1 += __shfl_xor_sync(0xffffffffu, v1, o);
        v2 += __shfl_xor_sync(0xffffffffu, v2, o);
        v3 += __shfl_xor_sync(0xffffffffu, v3, o);
    }
    __shared__ double sh[4][NT / 32];
    int lane = threadIdx.x & 31, wid = threadIdx.x >> 5;
    if (lane == 0) {
        sh[0][wid] = v0; sh[1][wid] = v1; sh[2][wid] = v2; sh[3][wid] = v3;
    }
    __syncthreads();
    if (threadIdx.x < 4) {
        double s = 0.0;
        #pragma unroll
        for (int k = 0; k < NT / 32; ++k) s += sh[threadIdx.x][k];
        double* tgt = (threadIdx.x == 0) ? t0 : (threadIdx.x == 1) ? t1
                    : (threadIdx.x == 2) ? t2 : t3;
        atomicAdd(tgt, s);
    }
}

__device__ __forceinline__ void block_reduce_max(float val, unsigned* target) {
    __syncthreads();
    #pragma unroll
    for (int o = 16; o; o >>= 1)
        val = fmaxf(val, __shfl_xor_sync(0xffffffffu, val, o));
    __shared__ float shm[NT / 32];
    int lane = threadIdx.x & 31, wid = threadIdx.x >> 5;
    if (lane == 0) shm[wid] = val;
    __syncthreads();
    if (threadIdx.x == 0) {
        float m = 0.f;
        #pragma unroll
        for (int k = 0; k < NT / 32; ++k) m = fmaxf(m, shm[k]);
        atomicMax(target, __float_as_uint(m));
    }
}

// software grid barrier (all GRID blocks co-resident by launch_bounds)
__device__ __forceinline__ void grid_sync() {
    __syncthreads();
    if (threadIdx.x == 0) {
        unsigned my = *(volatile unsigned*)&g_bar_gen;   // read BEFORE arrive
        __threadfence();
        if (atomicAdd(&g_bar_count, 1) == GRID - 1) {
            g_bar_count = 0;
            __threadfence();
            atomicAdd(&g_bar_gen, 1);
        } else {
            while (*(volatile unsigned*)&g_bar_gen == my) __nanosleep(64);
        }
        __threadfence();
    }
    __syncthreads();
}

__device__ __forceinline__ void decode(int sb, int t, int& i, int& z0,
                                       int& wi, int& h) {
    i  = (sb << 22) + (t * NT + (int)threadIdx.x) * 4;
    z0 = i & 63;
    wi = (i >> 6) & 255;
    h  = (i >> 14) & 255;
}

// ---------------------------------------------------------------------------
// kernels
// ---------------------------------------------------------------------------

__global__ void k_zero() {
    int t = threadIdx.x;
    if (t < (ITER + 1) * Bq) ((double*)g_rho)[t] = 0.0;
    if (t < ITER * Bq) {
        ((double*)g_eta)[t] = 0.0;
        ((double*)g_tau)[t] = 0.0;
        ((double*)g_om)[t]  = 0.0;
    }
    if (t == 0) { g_loss = 0.0; g_max = 0u; }
}

__global__ void __launch_bounds__(NT, 4)
k_cg(const float* __restrict__ x0, const float* __restrict__ bin,
     const float* __restrict__ ref, float* __restrict__ out) {
    const int sb   = blockIdx.x & 3;
    const int sblk = blockIdx.x >> 2;        // 0..SBLK-1
    const float4 Zv = make_float4(0.f, 0.f, 0.f, 0.f);
    __shared__ float s_a, s_b;

    // ---- P0 (asc): p0 = r0 = b - A x0 ; rho0 (direct) ----
    {
        float acc = 0.f;
        for (int t = sblk; t < TPS; t += SBLK) {
            int i, z0, wi, h; decode(sb, t, i, z0, wi, h);
            bool w1 = wi > 0, e1 = wi < Wq - 1, n1 = h > 0, s1 = h < Hq - 1;
            float4 xc = ld4(x0 + i);
            float4 xw = w1 ? ld4(x0 + i - Zq) : Zv;
            float4 xe = e1 ? ld4(x0 + i + Zq) : Zv;
            float4 xn = n1 ? ld4(x0 + i - WZ) : Zv;
            float4 xs = s1 ? ld4(x0 + i + WZ) : Zv;
            float4 ax = lap(xc, xw, xe, xn, xs, z0);
            float4 bb = ld4cs(bin + i);
            float4 r0 = make_float4(bb.x - ax.x, bb.y - ax.y,
                                    bb.z - ax.z, bb.w - ax.w);
            st4(g_p[0] + i, r0);
            acc += dot4(r0, r0);
        }
        block_reduce_add(acc, &g_rho[0][sb]);
    }
    grid_sync();

    // ---- P1 (desc): w0 = A p0 ; eta0 = p0.w0 ; tau0 = eta0 ; om0 = w0.w0 ----
    {
        float accE = 0.f, accO = 0.f;
        for (int t = sblk; t < TPS; t += SBLK) {
            int tt = TPS - 1 - t;
            int i, z0, wi, h; decode(sb, tt, i, z0, wi, h);
            bool w1 = wi > 0, e1 = wi < Wq - 1, n1 = h > 0, s1 = h < Hq - 1;
            const float* p0 = g_p[0];
            float4 pc = ld4(p0 + i);
            float4 pw = w1 ? ld4(p0 + i - Zq) : Zv;
            float4 pe = e1 ? ld4(p0 + i + Zq) : Zv;
            float4 pn4 = n1 ? ld4(p0 + i - WZ) : Zv;
            float4 ps4 = s1 ? ld4(p0 + i + WZ) : Zv;
            float4 w = lap(pc, pw, pe, pn4, ps4, z0);
            accE += dot4(pc, w);
            accO += dot4(w, w);
        }
        block_reduce4(accE, accE, accO, 0.f,
                      &g_eta[0][sb], &g_tau[0][sb], &g_om[0][sb],
                      &g_loss /* +0, harmless */);
    }
    grid_sync();

    // ---- fused phases k = 1..7: one phase per CG iteration ----
    for (int k = 1; k < ITER; ++k) {
        if (threadIdx.x == 0) {
            double rp = __ldcg(&g_rho[k - 1][sb]);
            double ep = __ldcg(&g_eta[k - 1][sb]);
            double tp = __ldcg(&g_tau[k - 1][sb]);
            double op = __ldcg(&g_om[k - 1][sb]);
            double al = rp / (ep + EPS);
            double rr = rp - 2.0 * al * tp + al * al * op;   // rho_k recurrence
            s_a = (float)al;
            s_b = (float)(rr / (rp + EPS));                  // beta_k
        }
        __syncthreads();
        const float al = s_a, bt = s_b;
        const float* rp_ = (k == 1) ? g_p[0] : g_r[k - 1];
        const float* pp  = g_p[k - 1];
        float* rout = g_r[k];
        float* pout = g_p[k];
        const bool rev = !(k & 1);
        float accR = 0.f, accE = 0.f, accT = 0.f, accO = 0.f;

        for (int t = sblk; t < TPS; t += SBLK) {
            int tt = rev ? TPS - 1 - t : t;
            int i, z0, wi, h; decode(sb, tt, i, z0, wi, h);
            bool w1 = wi > 0,     e1 = wi < Wq - 1;
            bool n1 = h  > 0,     s1 = h  < Hq - 1;
            bool w2 = wi > 1,     e2 = wi < Wq - 2;
            bool n2 = h  > 1,     s2 = h  < Hq - 2;

            // p: 13-point neighborhood
            float4 pc  = ld4(pp + i);
            float4 pw  = w1 ? ld4(pp + i - Zq) : Zv;
            float4 pe  = e1 ? ld4(pp + i + Zq) : Zv;
            float4 pn4 = n1 ? ld4(pp + i - WZ) : Zv;
            float4 ps4 = s1 ? ld4(pp + i + WZ) : Zv;
            float4 apc = lap(pc, pw, pe, pn4, ps4, z0);      // A p (direct)

            float4 pww = w2 ? ld4(pp + i - 2 * Zq) : Zv;
            float4 pnw = (w1 && n1) ? ld4(pp + i - Zq - WZ) : Zv;
            float4 psw = (w1 && s1) ? ld4(pp + i - Zq + WZ) : Zv;
            float4 apw = lap(pw, pww, pc, pnw, psw, z0);
            if (!w1) apw = Zv;

            float4 pee = e2 ? ld4(pp + i + 2 * Zq) : Zv;
            float4 pne = (e1 && n1) ? ld4(pp + i + Zq - WZ) : Zv;
            float4 pse = (e1 && s1) ? ld4(pp + i + Zq + WZ) : Zv;
            float4 ape = lap(pe, pc, pee, pne, pse, z0);
            if (!e1) ape = Zv;

            float4 pnn = n2 ? ld4(pp + i - 2 * WZ) : Zv;
            float4 apn = lap(pn4, pnw, pne, pnn, pc, z0);
            if (!n1) apn = Zv;

            float4 pss = s2 ? ld4(pp + i + 2 * WZ) : Zv;
            float4 aps = lap(ps4, psw, pse, pc, pss, z0);
            if (!s1) aps = Zv;

            float4 a2 = lap(apc, apw, ape, apn, aps, z0);    // A^2 p

            // r: 7-point
            float4 rc  = ld4(rp_ + i);
            float4 rw  = w1 ? ld4(rp_ + i - Zq) : Zv;
            float4 re4 = e1 ? ld4(rp_ + i + Zq) : Zv;
            float4 rn4 = n1 ? ld4(rp_ + i - WZ) : Zv;
            float4 rs4 = s1 ? ld4(rp_ + i + WZ) : Zv;
            float4 arc = lap(rc, rw, re4, rn4, rs4, z0);     // A r_{k-1}

            // r_k = r_{k-1} - alpha * A p_{k-1}
            float4 rk = make_float4(rc.x - al * apc.x, rc.y - al * apc.y,
                                    rc.z - al * apc.z, rc.w - al * apc.w);
            st4(rout + i, rk);
            accR += dot4(rk, rk);

            // A r_k = A r_{k-1} - alpha * A^2 p_{k-1}
            float4 ark = make_float4(arc.x - al * a2.x, arc.y - al * a2.y,
                                     arc.z - al * a2.z, arc.w - al * a2.w);
            // p_k = r_k + beta * p_{k-1}
            float4 pk = make_float4(rk.x + bt * pc.x, rk.y + bt * pc.y,
                                    rk.z + bt * pc.z, rk.w + bt * pc.w);
            st4(pout + i, pk);
            // w_k = A p_k = A r_k + beta * A p_{k-1}
            float4 wk = make_float4(ark.x + bt * apc.x, ark.y + bt * apc.y,
                                    ark.z + bt * apc.z, ark.w + bt * apc.w);
            accE += dot4(pk, wk);
            accT += dot4(rk, wk);
            accO += dot4(wk, wk);
        }
        block_reduce4(accR, accE, accT, accO,
                      &g_rho[k][sb], &g_eta[k][sb],
                      &g_tau[k][sb], &g_om[k][sb]);
        grid_sync();
    }

    // ---- final (desc): r8 = r7 - a7*A p7 (direct rho8);
    //      x = x0 + sum alpha_k p_k ; out / loss / max ----
    {
        __shared__ float s_alpha[ITER];
        if (threadIdx.x < ITER)
            s_alpha[threadIdx.x] =
                (float)(__ldcg(&g_rho[threadIdx.x][sb]) /
                        (__ldcg(&g_eta[threadIdx.x][sb]) + EPS));
        __syncthreads();
        const float a7 = s_alpha[ITER - 1];

        float accR = 0.f, accL = 0.f, mx = 0.f;
        for (int t = sblk; t < TPS; t += SBLK) {
            int tt = TPS - 1 - t;
            int i, z0, wi, h; decode(sb, tt, i, z0, wi, h);
            bool w1 = wi > 0, e1 = wi < Wq - 1, n1 = h > 0, s1 = h < Hq - 1;
            const float* p7 = g_p[ITER - 1];
            float4 pc  = ld4(p7 + i);
            float4 pw  = w1 ? ld4(p7 + i - Zq) : Zv;
            float4 pe  = e1 ? ld4(p7 + i + Zq) : Zv;
            float4 pn4 = n1 ? ld4(p7 + i - WZ) : Zv;
            float4 ps4 = s1 ? ld4(p7 + i + WZ) : Zv;
            float4 w7 = lap(pc, pw, pe, pn4, ps4, z0);
            float4 r7 = ld4(g_r[ITER - 1] + i);
            float4 r8 = make_float4(r7.x - a7 * w7.x, r7.y - a7 * w7.y,
                                    r7.z - a7 * w7.z, r7.w - a7 * w7.w);
            accR += dot4(r8, r8);

            float4 x = ld4cs(x0 + i);
            #pragma unroll
            for (int k = 0; k < ITER - 1; ++k) {
                float a = s_alpha[k];
                float4 pk = ld4cs(g_p[k] + i);
                x.x += a * pk.x; x.y += a * pk.y;
                x.z += a * pk.z; x.w += a * pk.w;
            }
            x.x += a7 * pc.x; x.y += a7 * pc.y;
            x.z += a7 * pc.z; x.w += a7 * pc.w;

            __stcs(out + 1 + i + 0, x.x);
            __stcs(out + 1 + i + 1, x.y);
            __stcs(out + 1 + i + 2, x.z);
            __stcs(out + 1 + i + 3, x.w);

            float4 rf = ld4cs(ref + i);
            float dx = x.x - rf.x, dy = x.y - rf.y;
            float dz = x.z - rf.z, dw = x.w - rf.w;
            accL += dx * dx + dy * dy + dz * dz + dw * dw;
            mx = fmaxf(mx, fmaxf(fmaxf(fabsf(dx), fabsf(dy)),
                                 fmaxf(fabsf(dz), fabsf(dw))));
        }
        block_reduce_add(accR, &g_rho[ITER][sb]);
        block_reduce_add(accL, &g_loss);
        block_reduce_max(mx, &g_max);
    }
}

__global__ void k_writeout(float* __restrict__ out) {
    out[0] = (float)(g_loss / (double)N);
    out[N + 1] = __uint_as_float(g_max);
    double s = 0.0;
    #pragma unroll
    for (int b = 0; b < Bq; ++b) s += g_rho[ITER][b];
    out[N + 2] = (float)(s / (double)Bq);
}

// ---------------------------------------------------------------------------

extern "C" void kernel_launch(void* const* d_in, const int* in_sizes, int n_in,
                              void* d_out, int out_size) {
    const float* x   = (const float*)d_in[0];
    const float* b   = (const float*)d_in[1];
    const float* ref = (const float*)d_in[2];
    float* out = (float*)d_out;

    k_zero<<<1, 64>>>();
    k_cg<<<GRID, NT>>>(x, b, ref, out);
    k_writeout<<<1, 1>>>(out);
}

// round 11
// speedup vs baseline: 4.6893x; 1.0212x over previous
#include <cuda_runtime.h>

// Problem constants
#define Bq 4
#define Hq 256
#define Wq 256
#define Zq 64
#define ITER 8
#define EPS 1e-6

constexpr int N    = Bq * Hq * Wq * Zq;   // 16,777,216
constexpr int SAMP = Hq * Wq * Zq;        // 4,194,304
#define NT 256
constexpr int GRID = 592;                 // 148 SMs x 4 blocks co-resident
constexpr int SBLK = GRID / Bq;           // 148 blocks per sample
constexpr int TPS  = SAMP / (NT * 4);     // 4096 tiles per sample
constexpr int WZ   = Wq * Zq;

// Scratch (device globals; allocation forbidden). Write-once buffer
// versioning -> no stale-L1 hazard inside the persistent kernel.
__device__ float g_p[ITER][N];   // p_0..p_7 (r_k = p_k - beta_k p_{k-1})

__device__ double   g_rho[ITER + 1][Bq];  // direct dots r_k.r_k
__device__ double   g_eta[ITER][Bq];      // p_k . w_k
__device__ double   g_tau[ITER][Bq];      // r_k . w_k
__device__ double   g_om [ITER][Bq];      // w_k . w_k
__device__ double   g_loss;
__device__ unsigned g_max;

__device__ unsigned g_bar_count;          // self-resetting
__device__ unsigned g_bar_gen;            // monotonic across replays

// ---------------------------------------------------------------------------
// helpers
// ---------------------------------------------------------------------------

__device__ __forceinline__ float4 ld4(const float* __restrict__ p) {
    return *reinterpret_cast<const float4*>(p);
}
__device__ __forceinline__ float4 ld4cs(const float* __restrict__ p) {
    return __ldcs(reinterpret_cast<const float4*>(p));
}
__device__ __forceinline__ void st4(float* __restrict__ p, float4 v) {
    *reinterpret_cast<float4*>(p) = v;
}
__device__ __forceinline__ float dot4(float4 a, float4 b) {
    return a.x * b.x + a.y * b.y + a.z * b.z + a.w * b.w;
}

// 7-pt Laplacian of quad c given 4 side quads; z-neighbors via lane shuffle
// (16 lanes tile one z-line; boundary shuffles masked by z0).
// MUST be called unconditionally by all lanes (shuffles inside).
__device__ __forceinline__ float4 lap(float4 c, float4 xm, float4 xp,
                                      float4 ym, float4 yp, int z0) {
    float zl = __shfl_up_sync(0xffffffffu, c.w, 1);
    float zr = __shfl_down_sync(0xffffffffu, c.x, 1);
    if (z0 == 0)  zl = 0.f;
    if (z0 == 60) zr = 0.f;
    float4 o;
    o.x = 6.f * c.x - xm.x - xp.x - ym.x - yp.x - zl  - c.y;
    o.y = 6.f * c.y - xm.y - xp.y - ym.y - yp.y - c.x - c.z;
    o.z = 6.f * c.z - xm.z - xp.z - ym.z - yp.z - c.y - c.w;
    o.w = 6.f * c.w - xm.w - xp.w - ym.w - yp.w - c.z - zr;
    return o;
}

__device__ __forceinline__ void block_reduce_add(float val, double* target) {
    __syncthreads();
    #pragma unroll
    for (int o = 16; o; o >>= 1)
        val += __shfl_xor_sync(0xffffffffu, val, o);
    __shared__ double sh[NT / 32];
    int lane = threadIdx.x & 31, wid = threadIdx.x >> 5;
    if (lane == 0) sh[wid] = (double)val;
    __syncthreads();
    if (threadIdx.x == 0) {
        double s = 0.0;
        #pragma unroll
        for (int k = 0; k < NT / 32; ++k) s += sh[k];
        atomicAdd(target, s);
    }
}

__device__ __forceinline__ void block_reduce4(float v0, float v1, float v2,
                                              float v3, double* t0, double* t1,
                                              double* t2, double* t3) {
    __syncthreads();
    #pragma unroll
    for (int o = 16; o; o >>= 1) {
        v0 += __shfl_xor_sync(0xffffffffu, v0, o);
        v1 += __shfl_xor_sync(0xffffffffu, v1, o);
        v2 += __shfl_xor_sync(0xffffffffu, v2, o);
        v3 += __shfl_xor_sync(0xffffffffu, v3, o);
    }
    __shared__ double sh[4][NT / 32];
    int lane = threadIdx.x & 31, wid = threadIdx.x >> 5;
    if (lane == 0) {
        sh[0][wid] = v0; sh[1][wid] = v1; sh[2][wid] = v2; sh[3][wid] = v3;
    }
    __syncthreads();
    if (threadIdx.x < 4) {
        double s = 0.0;
        #pragma unroll
        for (int k = 0; k < NT / 32; ++k) s += sh[threadIdx.x][k];
        double* tgt = (threadIdx.x == 0) ? t0 : (threadIdx.x == 1) ? t1
                    : (threadIdx.x == 2) ? t2 : t3;
        atomicAdd(tgt, s);
    }
}

__device__ __forceinline__ void block_reduce_max(float val, unsigned* target) {
    __syncthreads();
    #pragma unroll
    for (int o = 16; o; o >>= 1)
        val = fmaxf(val, __shfl_xor_sync(0xffffffffu, val, o));
    __shared__ float shm[NT / 32];
    int lane = threadIdx.x & 31, wid = threadIdx.x >> 5;
    if (lane == 0) shm[wid] = val;
    __syncthreads();
    if (threadIdx.x == 0) {
        float m = 0.f;
        #pragma unroll
        for (int k = 0; k < NT / 32; ++k) m = fmaxf(m, shm[k]);
        atomicMax(target, __float_as_uint(m));
    }
}

// software grid barrier (all GRID blocks co-resident by launch_bounds)
__device__ __forceinline__ void grid_sync() {
    __syncthreads();
    if (threadIdx.x == 0) {
        unsigned my = *(volatile unsigned*)&g_bar_gen;   // read BEFORE arrive
        __threadfence();
        if (atomicAdd(&g_bar_count, 1) == GRID - 1) {
            g_bar_count = 0;
            __threadfence();
            atomicAdd(&g_bar_gen, 1);
        } else {
            while (*(volatile unsigned*)&g_bar_gen == my) __nanosleep(64);
        }
        __threadfence();
    }
    __syncthreads();
}

__device__ __forceinline__ void decode(int sb, int t, int& i, int& z0,
                                       int& wi, int& h) {
    i  = (sb << 22) + (t * NT + (int)threadIdx.x) * 4;
    z0 = i & 63;
    wi = (i >> 6) & 255;
    h  = (i >> 14) & 255;
}

// scalars for iteration j (>=1 deps): alpha_{j} & beta_{j+1} from dots of j.
// DOUBLE math, identical op order everywhere -> deterministic recompute.
__device__ __forceinline__ void scal_ab(int j, int sb, double& al, double& bt) {
    double r = __ldcg(&g_rho[j][sb]);
    double e = __ldcg(&g_eta[j][sb]);
    double t = __ldcg(&g_tau[j][sb]);
    double o = __ldcg(&g_om [j][sb]);
    al = r / (e + EPS);
    double rr = r - 2.0 * al * t + al * al * o;    // rho_{j+1} recurrence
    bt = rr / (r + EPS);                           // beta_{j+1}
}

// ---------------------------------------------------------------------------
// kernels
// ---------------------------------------------------------------------------

__global__ void k_zero() {
    int t = threadIdx.x;
    if (t < (ITER + 1) * Bq) ((double*)g_rho)[t] = 0.0;
    if (t < ITER * Bq) {
        ((double*)g_eta)[t] = 0.0;
        ((double*)g_tau)[t] = 0.0;
        ((double*)g_om)[t]  = 0.0;
    }
    if (t == 0) { g_loss = 0.0; g_max = 0u; }
}

__global__ void __launch_bounds__(NT, 4)
k_cg(const float* __restrict__ x0, const float* __restrict__ bin,
     const float* __restrict__ ref, float* __restrict__ out) {
    const int sb   = blockIdx.x & 3;
    const int sblk = blockIdx.x >> 2;
    const float4 Zv = make_float4(0.f, 0.f, 0.f, 0.f);
    __shared__ float s_a, s_bk, s_bp;

    // ---- P0 (asc): p0 = r0 = b - A x0 ; rho0 (direct) ----
    {
        float acc = 0.f;
        for (int t = sblk; t < TPS; t += SBLK) {
            int i, z0, wi, h; decode(sb, t, i, z0, wi, h);
            bool w1 = wi > 0, e1 = wi < Wq - 1, n1 = h > 0, s1 = h < Hq - 1;
            float4 xc = ld4(x0 + i);
            float4 xw = w1 ? ld4(x0 + i - Zq) : Zv;
            float4 xe = e1 ? ld4(x0 + i + Zq) : Zv;
            float4 xn = n1 ? ld4(x0 + i - WZ) : Zv;
            float4 xs = s1 ? ld4(x0 + i + WZ) : Zv;
            float4 ax = lap(xc, xw, xe, xn, xs, z0);
            float4 bb = ld4cs(bin + i);
            float4 r0 = make_float4(bb.x - ax.x, bb.y - ax.y,
                                    bb.z - ax.z, bb.w - ax.w);
            st4(g_p[0] + i, r0);
            acc += dot4(r0, r0);
        }
        block_reduce_add(acc, &g_rho[0][sb]);
    }
    grid_sync();

    // ---- P1 (desc): w0 = A p0 ; eta0 = tau0 = p0.w0 ; om0 = w0.w0 ----
    {
        float accE = 0.f, accO = 0.f;
        for (int t = sblk; t < TPS; t += SBLK) {
            int tt = TPS - 1 - t;
            int i, z0, wi, h; decode(sb, tt, i, z0, wi, h);
            bool w1 = wi > 0, e1 = wi < Wq - 1, n1 = h > 0, s1 = h < Hq - 1;
            const float* p0 = g_p[0];
            float4 pc  = ld4(p0 + i);
            float4 pw  = w1 ? ld4(p0 + i - Zq) : Zv;
            float4 pe  = e1 ? ld4(p0 + i + Zq) : Zv;
            float4 pn4 = n1 ? ld4(p0 + i - WZ) : Zv;
            float4 ps4 = s1 ? ld4(p0 + i + WZ) : Zv;
            float4 w = lap(pc, pw, pe, pn4, ps4, z0);
            accE += dot4(pc, w);
            accO += dot4(w, w);
        }
        block_reduce4(accE, accE, accO, 0.f,
                      &g_eta[0][sb], &g_tau[0][sb], &g_om[0][sb], &g_loss);
    }
    grid_sync();

    // ---- fused phases k = 1..7 (p-only state) ----
    for (int k = 1; k < ITER; ++k) {
        if (threadIdx.x == 0) {
            double al, bk;
            scal_ab(k - 1, sb, al, bk);           // alpha_{k-1}, beta_k
            s_a = (float)al; s_bk = (float)bk;
            if (k >= 2) {
                double ap, bp;
                scal_ab(k - 2, sb, ap, bp);       // -> beta_{k-1}
                s_bp = (float)bp;
            }
        }
        __syncthreads();
        const float al = s_a, bk = s_bk, bp = (k >= 2) ? s_bp : 0.f;
        const float* pp = g_p[k - 1];
        const float* qq = (k >= 2) ? g_p[k - 2] : nullptr;
        float* pout = g_p[k];
        const bool rev = !(k & 1);
        float accR = 0.f, accE = 0.f, accT = 0.f, accO = 0.f;

        for (int t = sblk; t < TPS; t += SBLK) {
            int tt = rev ? TPS - 1 - t : t;
            int i, z0, wi, h; decode(sb, tt, i, z0, wi, h);
            bool w1 = wi > 0,  e1 = wi < Wq - 1;
            bool n1 = h  > 0,  s1 = h  < Hq - 1;
            bool w2 = wi > 1,  e2 = wi < Wq - 2;
            bool n2 = h  > 1,  s2 = h  < Hq - 2;

            // p_{k-1}: 13-point neighborhood -> A p, A^2 p
            float4 pc  = ld4(pp + i);
            float4 pw  = w1 ? ld4(pp + i - Zq) : Zv;
            float4 pe  = e1 ? ld4(pp + i + Zq) : Zv;
            float4 pn4 = n1 ? ld4(pp + i - WZ) : Zv;
            float4 ps4 = s1 ? ld4(pp + i + WZ) : Zv;
            float4 apc = lap(pc, pw, pe, pn4, ps4, z0);      // A p_{k-1}

            float4 pww = w2 ? ld4(pp + i - 2 * Zq) : Zv;
            float4 pnw = (w1 && n1) ? ld4(pp + i - Zq - WZ) : Zv;
            float4 psw = (w1 && s1) ? ld4(pp + i - Zq + WZ) : Zv;
            float4 apw = lap(pw, pww, pc, pnw, psw, z0);
            if (!w1) apw = Zv;

            float4 pee = e2 ? ld4(pp + i + 2 * Zq) : Zv;
            float4 pne = (e1 && n1) ? ld4(pp + i + Zq - WZ) : Zv;
            float4 pse = (e1 && s1) ? ld4(pp + i + Zq + WZ) : Zv;
            float4 ape = lap(pe, pc, pee, pne, pse, z0);
            if (!e1) ape = Zv;

            float4 pnn = n2 ? ld4(pp + i - 2 * WZ) : Zv;
            float4 apn = lap(pn4, pnw, pne, pnn, pc, z0);
            if (!n1) apn = Zv;

            float4 pss = s2 ? ld4(pp + i + 2 * WZ) : Zv;
            float4 aps = lap(ps4, psw, pse, pc, pss, z0);
            if (!s1) aps = Zv;

            float4 a2 = lap(apc, apw, ape, apn, aps, z0);    // A^2 p_{k-1}

            // r_{k-1} = p_{k-1} - beta_{k-1} p_{k-2} ; A r likewise (linear)
            float4 rc, arc;
            if (k == 1) {
                rc = pc; arc = apc;                           // r_0 == p_0
            } else {
                float4 qc  = ld4(qq + i);
                float4 qw  = w1 ? ld4(qq + i - Zq) : Zv;
                float4 qe  = e1 ? ld4(qq + i + Zq) : Zv;
                float4 qn4 = n1 ? ld4(qq + i - WZ) : Zv;
                float4 qs4 = s1 ? ld4(qq + i + WZ) : Zv;
                float4 aqc = lap(qc, qw, qe, qn4, qs4, z0);   // A p_{k-2}
                rc  = make_float4(pc.x - bp * qc.x,  pc.y - bp * qc.y,
                                  pc.z - bp * qc.z,  pc.w - bp * qc.w);
                arc = make_float4(apc.x - bp * aqc.x, apc.y - bp * aqc.y,
                                  apc.z - bp * aqc.z, apc.w - bp * aqc.w);
            }

            // r_k = r_{k-1} - alpha * A p_{k-1}
            float4 rk = make_float4(rc.x - al * apc.x, rc.y - al * apc.y,
                                    rc.z - al * apc.z, rc.w - al * apc.w);
            accR += dot4(rk, rk);
            // A r_k = A r_{k-1} - alpha * A^2 p_{k-1}
            float4 ark = make_float4(arc.x - al * a2.x, arc.y - al * a2.y,
                                     arc.z - al * a2.z, arc.w - al * a2.w);
            // p_k = r_k + beta_k * p_{k-1}
            float4 pk = make_float4(rk.x + bk * pc.x, rk.y + bk * pc.y,
                                    rk.z + bk * pc.z, rk.w + bk * pc.w);
            st4(pout + i, pk);
            // w_k = A p_k = A r_k + beta_k * A p_{k-1}
            float4 wk = make_float4(ark.x + bk * apc.x, ark.y + bk * apc.y,
                                    ark.z + bk * apc.z, ark.w + bk * apc.w);
            accE += dot4(pk, wk);
            accT += dot4(rk, wk);
            accO += dot4(wk, wk);
        }
        block_reduce4(accR, accE, accT, accO,
                      &g_rho[k][sb], &g_eta[k][sb],
                      &g_tau[k][sb], &g_om[k][sb]);
        grid_sync();
    }

    // ---- final (desc): r8 via r7 = p7 - beta7 p6 ; x = x0 + sum a_k p_k ----
    {
        __shared__ float s_alpha[ITER], s_b7;
        if (threadIdx.x < ITER)
            s_alpha[threadIdx.x] =
                (float)(__ldcg(&g_rho[threadIdx.x][sb]) /
                        (__ldcg(&g_eta[threadIdx.x][sb]) + EPS));
        if (threadIdx.x == 0) {
            double a6, b7;
            scal_ab(ITER - 2, sb, a6, b7);        // beta_7
            s_b7 = (float)b7;
        }
        __syncthreads();
        const float a7 = s_alpha[ITER - 1], b7 = s_b7;

        float accR = 0.f, accL = 0.f, mx = 0.f;
        for (int t = sblk; t < TPS; t += SBLK) {
            int tt = TPS - 1 - t;
            int i, z0, wi, h; decode(sb, tt, i, z0, wi, h);
            bool w1 = wi > 0, e1 = wi < Wq - 1, n1 = h > 0, s1 = h < Hq - 1;
            const float* p7 = g_p[ITER - 1];
            float4 pc  = ld4(p7 + i);
            float4 pw  = w1 ? ld4(p7 + i - Zq) : Zv;
            float4 pe  = e1 ? ld4(p7 + i + Zq) : Zv;
            float4 pn4 = n1 ? ld4(p7 + i - WZ) : Zv;
            float4 ps4 = s1 ? ld4(p7 + i + WZ) : Zv;
            float4 w7 = lap(pc, pw, pe, pn4, ps4, z0);

            float4 x = ld4cs(x0 + i);
            float4 p6c;
            #pragma unroll
            for (int k = 0; k < ITER - 1; ++k) {
                float a = s_alpha[k];
                float4 pk = ld4cs(g_p[k] + i);
                if (k == ITER - 2) p6c = pk;
                x.x += a * pk.x; x.y += a * pk.y;
                x.z += a * pk.z; x.w += a * pk.w;
            }
            x.x += a7 * pc.x; x.y += a7 * pc.y;
            x.z += a7 * pc.z; x.w += a7 * pc.w;

            // r7 = p7 - b7 * p6 ; r8 = r7 - a7 * w7
            float4 r8 = make_float4(pc.x - b7 * p6c.x - a7 * w7.x,
                                    pc.y - b7 * p6c.y - a7 * w7.y,
                                    pc.z - b7 * p6c.z - a7 * w7.z,
                                    pc.w - b7 * p6c.w - a7 * w7.w);
            accR += dot4(r8, r8);

            __stcs(out + 1 + i + 0, x.x);
            __stcs(out + 1 + i + 1, x.y);
            __stcs(out + 1 + i + 2, x.z);
            __stcs(out + 1 + i + 3, x.w);

            float4 rf = ld4cs(ref + i);
            float dx = x.x - rf.x, dy = x.y - rf.y;
            float dz = x.z - rf.z, dw = x.w - rf.w;
            accL += dx * dx + dy * dy + dz * dz + dw * dw;
            mx = fmaxf(mx, fmaxf(fmaxf(fabsf(dx), fabsf(dy)),
                                 fmaxf(fabsf(dz), fabsf(dw))));
        }
        block_reduce_add(accR, &g_rho[ITER][sb]);
        block_reduce_add(accL, &g_loss);
        block_reduce_max(mx, &g_max);
    }
}

__global__ void k_writeout(float* __restrict__ out) {
    out[0] = (float)(g_loss / (double)N);
    out[N + 1] = __uint_as_float(g_max);
    double s = 0.0;
    #pragma unroll
    for (int b = 0; b < Bq; ++b) s += g_rho[ITER][b];
    out[N + 2] = (float)(s / (double)Bq);
}

// ---------------------------------------------------------------------------

extern "C" void kernel_launch(void* const* d_in, const int* in_sizes, int n_in,
                              void* d_out, int out_size) {
    const float* x   = (const float*)d_in[0];
    const float* b   = (const float*)d_in[1];
    const float* ref = (const float*)d_in[2];
    float* out = (float*)d_out;

    k_zero<<<1, 64>>>();
    k_cg<<<GRID, NT>>>(x, b, ref, out);
    k_writeout<<<1, 1>>>(out);
}